// round 6
// baseline (speedup 1.0000x reference)
#include <cuda_runtime.h>
#include <cuda_bf16.h>
#include <math.h>
#include <stdint.h>

// Problem constants
#define D    80
#define E    8
#define HID  320
#define NL   4
#define TBK  128           // tokens per ffn block (2 tiles of 64)
#define NCK  5             // HID chunks of 64
#define MAXT 131072
#define RTB  32            // router tokens per block

// smem row strides (elements) — odd multiples of 8 -> conflict-free ldmatrix
#define XS   88
#define W1S  72
#define HS   72
#define W2S  88

// smem layout (bytes)
#define SM_STOK 0
#define SM_SWT  512
#define SM_SB1  1024
#define SM_SB2  1280
#define SM_XHI  1664
#define SM_XLO  (SM_XHI  + TBK * XS * 2)     // 24192
#define SM_W1HI (SM_XLO  + TBK * XS * 2)     // 46720
#define SM_W1LO (SM_W1HI + 80 * W1S * 2)     // 58240
#define SM_W2HI (SM_W1LO + 80 * W1S * 2)     // 69760
#define SM_W2LO (SM_W2HI + 64 * W2S * 2)     // 81024
#define SM_HHI  (SM_W2LO + 64 * W2S * 2)     // 92288  (per-tile H: 64 rows)
#define SM_HLO  (SM_HHI  + 64 * HS * 2)      // 101504
#define SMEM_TOTAL (SM_HLO + 64 * HS * 2)    // 110720

// ---------------------------------------------------------------------------
// Scratch (no cudaMalloc allowed)
// ---------------------------------------------------------------------------
__device__ float g_bufA[MAXT * D];
__device__ float g_bufB[MAXT * D];
__device__ int   g_cnt[E];
__device__ int   g_tok[E * MAXT];
__device__ float g_wt [E * MAXT];
// split-bf16 weights, natural layouts
__device__ __align__(16) unsigned short g_w1h[E * D * HID];   // [e][d][h]
__device__ __align__(16) unsigned short g_w1l[E * D * HID];
__device__ __align__(16) unsigned short g_w2h[E * HID * D];   // [e][h][d]
__device__ __align__(16) unsigned short g_w2l[E * HID * D];

// ---------------------------------------------------------------------------
// PTX helpers (sm_80-era: valid on compute_100 without the 'a' suffix)
// ---------------------------------------------------------------------------
__device__ __forceinline__ uint32_t smem_u32(const void* p) {
    uint32_t a;
    asm("{ .reg .u64 t; cvta.to.shared.u64 t, %1; cvt.u32.u64 %0, t; }" : "=r"(a) : "l"(p));
    return a;
}
__device__ __forceinline__ void ldsm4(uint32_t* r, uint32_t a) {
    asm volatile("ldmatrix.sync.aligned.m8n8.x4.shared.b16 {%0,%1,%2,%3}, [%4];"
        : "=r"(r[0]), "=r"(r[1]), "=r"(r[2]), "=r"(r[3]) : "r"(a));
}
__device__ __forceinline__ void ldsm4t(uint32_t* r, uint32_t a) {
    asm volatile("ldmatrix.sync.aligned.m8n8.x4.trans.shared.b16 {%0,%1,%2,%3}, [%4];"
        : "=r"(r[0]), "=r"(r[1]), "=r"(r[2]), "=r"(r[3]) : "r"(a));
}
__device__ __forceinline__ void ldsm2t(uint32_t* r, uint32_t a) {
    asm volatile("ldmatrix.sync.aligned.m8n8.x2.trans.shared.b16 {%0,%1}, [%2];"
        : "=r"(r[0]), "=r"(r[1]) : "r"(a));
}
__device__ __forceinline__ void mma_bf16(float* c, const uint32_t* a, const uint32_t* b) {
    asm volatile("mma.sync.aligned.m16n8k16.row.col.f32.bf16.bf16.f32 "
        "{%0,%1,%2,%3}, {%4,%5,%6,%7}, {%8,%9}, {%0,%1,%2,%3};"
        : "+f"(c[0]), "+f"(c[1]), "+f"(c[2]), "+f"(c[3])
        : "r"(a[0]), "r"(a[1]), "r"(a[2]), "r"(a[3]), "r"(b[0]), "r"(b[1]));
}

// ---------------------------------------------------------------------------
// Weight prep: elementwise split fp32 -> bf16 hi + lo
// ---------------------------------------------------------------------------
__global__ void prep_kernel(const float* __restrict__ W1, const float* __restrict__ W2) {
    int i = blockIdx.x * blockDim.x + threadIdx.x;
    const int N1 = E * D * HID;
    const int N2 = E * HID * D;
    if (i < N1) {
        float v = W1[i];
        __nv_bfloat16 h = __float2bfloat16(v);
        __nv_bfloat16 l = __float2bfloat16(v - __bfloat162float(h));
        g_w1h[i] = *(unsigned short*)&h;
        g_w1l[i] = *(unsigned short*)&l;
    } else if (i < N1 + N2) {
        int j = i - N1;
        float v = W2[j];
        __nv_bfloat16 h = __float2bfloat16(v);
        __nv_bfloat16 l = __float2bfloat16(v - __bfloat162float(h));
        g_w2h[j] = *(unsigned short*)&h;
        g_w2l[j] = *(unsigned short*)&l;
    }
}

// ---------------------------------------------------------------------------
// Router: 32 tokens/block (grid ~750 -> high SM parallelism), coalesced smem
// staging, fused lout zeroing. Exact jax top_k tie semantics; raw logits = weights.
// ---------------------------------------------------------------------------
__global__ void __launch_bounds__(128)
router_kernel(const float* __restrict__ x,
              const float* __restrict__ Wg,
              const float* __restrict__ bg,
              float* __restrict__ lout, int T) {
    __shared__ float wg[D * E];
    __shared__ float bgs[E];
    __shared__ float xs[RTB * 81];

    int tid  = threadIdx.x;
    int base = blockIdx.x * RTB;
    int ntok = T - base; if (ntok > RTB) ntok = RTB;
    if (ntok <= 0) return;

    for (int i = tid; i < D * E; i += 128) wg[i] = Wg[i];
    if (tid < E) bgs[tid] = bg[tid];

    // stage X (coalesced float4) + zero this block's slice of lout
    {
        const float4* gx = (const float4*)(x + (size_t)base * D);
        float4*       gz = (float4*)(lout + (size_t)base * D);
        int n4 = ntok * (D / 4);
        const float4 z = make_float4(0.f, 0.f, 0.f, 0.f);
        for (int i = tid; i < n4; i += 128) {
            float4 v = gx[i];
            gz[i] = z;
            int r = i / 20, c = (i - r * 20) * 4;
            float* dst = &xs[r * 81 + c];
            dst[0] = v.x; dst[1] = v.y; dst[2] = v.z; dst[3] = v.w;
        }
    }
    __syncthreads();

    if (tid >= ntok) return;
    int t = base + tid;

    float acc[E];
    #pragma unroll
    for (int e = 0; e < E; e++) acc[e] = bgs[e];
    const float* xr = &xs[tid * 81];
    #pragma unroll 4
    for (int k = 0; k < D; k++) {
        float xv = xr[k];
        #pragma unroll
        for (int e = 0; e < E; e++) acc[e] = fmaf(xv, wg[k * E + e], acc[e]);
    }
    float v0 = -INFINITY, v1 = -INFINITY; int i0 = 0, i1 = 0;
    #pragma unroll
    for (int e = 0; e < E; e++) {
        float v = acc[e];
        if (v > v0)      { v1 = v0; i1 = i0; v0 = v; i0 = e; }
        else if (v > v1) { v1 = v;  i1 = e; }
    }
    int p0 = atomicAdd(&g_cnt[i0], 1);
    g_tok[i0 * MAXT + p0] = t;  g_wt[i0 * MAXT + p0] = v0;
    int p1 = atomicAdd(&g_cnt[i1], 1);
    g_tok[i1 * MAXT + p1] = t;  g_wt[i1 * MAXT + p1] = v1;
}

// ---------------------------------------------------------------------------
// FFN: 128 tokens (two 64-token tiles) of one expert per block.
// Weight tiles staged once per chunk serve both tiles -> L2 traffic halved.
// ---------------------------------------------------------------------------
__global__ void __launch_bounds__(256, 2)
ffn_kernel(const float* __restrict__ in,  float* __restrict__ out,
           const float* __restrict__ b1,  const float* __restrict__ b2) {
    extern __shared__ char smem[];
    uint32_t sb = smem_u32(smem);
    int tid  = threadIdx.x;
    int lane = tid & 31;
    int wid  = tid >> 5;

    int e = blockIdx.y;
    int n = g_cnt[e];
    int start = blockIdx.x * TBK;
    if (start >= n) return;
    bool has2 = (n > start + 64);

    int*   stok = (int*)  (smem + SM_STOK);
    float* swt  = (float*)(smem + SM_SWT);
    float* sb1  = (float*)(smem + SM_SB1);
    float* sb2  = (float*)(smem + SM_SB2);

    if (tid < TBK) {
        int p = start + tid;
        if (p < n) { stok[tid] = g_tok[e * MAXT + p]; swt[tid] = g_wt[e * MAXT + p]; }
        else       { stok[tid] = -1; swt[tid] = 0.f; }
    }
    if (tid < D) sb2[tid] = b2[e * D + tid];
    __syncthreads();

    // ---- gather X, split into bf16 hi/lo smem (2 threads per token, 128 tok) ----
    {
        int r = tid >> 1, half = tid & 1;
        int tk = stok[r];
        const float* xr = in + (size_t)(tk < 0 ? 0 : tk) * D + half * 40;
        char* dh = smem + SM_XHI + (r * XS + half * 40) * 2;
        char* dl = smem + SM_XLO + (r * XS + half * 40) * 2;
        #pragma unroll
        for (int j = 0; j < 20; j++) {
            float2 v = (tk >= 0) ? *(const float2*)&xr[2 * j] : make_float2(0.f, 0.f);
            __nv_bfloat162 h2 = __floats2bfloat162_rn(v.x, v.y);
            float2 hf = __bfloat1622float2(h2);
            __nv_bfloat162 l2 = __floats2bfloat162_rn(v.x - hf.x, v.y - hf.y);
            *(uint32_t*)(dh + 4 * j) = *(uint32_t*)&h2;
            *(uint32_t*)(dl + 4 * j) = *(uint32_t*)&l2;
        }
    }

    // warp tiling: 4 (M within 64-tile) x 2 (N)
    int warp_m = wid >> 1;
    int warp_n = wid & 1;
    int m_base = warp_m * 16;

    uint32_t aX    = sb + SM_XHI  + ((m_base + (lane & 15)) * XS + (lane >> 4) * 8) * 2;
    uint32_t aH    = sb + SM_HHI  + ((m_base + (lane & 15)) * HS + (lane >> 4) * 8) * 2;
    uint32_t bW1_4 = sb + SM_W1HI + ((lane & 15) * W1S + warp_n * 32 + (lane >> 4) * 8) * 2;
    uint32_t bW2_4 = sb + SM_W2HI + ((lane & 15) * W2S + warp_n * 40 + (lane >> 4) * 8) * 2;
    uint32_t bW2_2 = sb + SM_W2HI + ((lane & 15) * W2S + warp_n * 40 + 32) * 2;
    const int dXlo  = SM_XLO  - SM_XHI;
    const int dW1lo = SM_W1LO - SM_W1HI;
    const int dHlo  = SM_HLO  - SM_HHI;
    const int dW2lo = SM_W2LO - SM_W2HI;
    const int XTILE = 64 * XS * 2;   // byte offset of tile 1 in X

    // GEMM2 accumulators: [tile][n-atom][frag]
    float yacc[2][5][4];
    #pragma unroll
    for (int t = 0; t < 2; t++)
        #pragma unroll
        for (int na = 0; na < 5; na++)
            #pragma unroll
            for (int i = 0; i < 4; i++) yacc[t][na][i] = 0.f;

    const unsigned short* w1hB = g_w1h + e * D * HID;
    const unsigned short* w1lB = g_w1l + e * D * HID;
    const unsigned short* w2hB = g_w2h + e * HID * D;
    const unsigned short* w2lB = g_w2l + e * HID * D;

    for (int c = 0; c < NCK; c++) {
        // ---- stage weight tiles into smem (used by BOTH token tiles) ----
        {
            const unsigned short* s1h = w1hB + c * 64;
            const unsigned short* s1l = w1lB + c * 64;
            #pragma unroll 2
            for (int idx = tid; idx < 640; idx += 256) {
                int row = idx >> 3, v = idx & 7;
                int dsto = (row * W1S + v * 8) * 2;
                int srco = row * HID + v * 8;
                *(uint4*)(smem + SM_W1HI + dsto) = *(const uint4*)(s1h + srco);
                *(uint4*)(smem + SM_W1LO + dsto) = *(const uint4*)(s1l + srco);
            }
            const unsigned short* s2h = w2hB + c * 64 * D;
            const unsigned short* s2l = w2lB + c * 64 * D;
            #pragma unroll 2
            for (int idx = tid; idx < 640; idx += 256) {
                int row = idx / 10, v = idx - row * 10;
                int dsto = (row * W2S + v * 8) * 2;
                int srco = row * D + v * 8;
                *(uint4*)(smem + SM_W2HI + dsto) = *(const uint4*)(s2h + srco);
                *(uint4*)(smem + SM_W2LO + dsto) = *(const uint4*)(s2l + srco);
            }
            if (tid < 64) sb1[tid] = b1[e * HID + c * 64 + tid];
        }
        __syncthreads();

        #pragma unroll
        for (int t = 0; t < 2; t++) {
            if (t == 1 && !has2) break;   // block-uniform: barrier counts stay consistent
            uint32_t aXt = aX + t * XTILE;

            // ---- GEMM1: acc = Xtile(64x80) @ W1chunk(80x64), 3-term split ----
            float acc[4][4];
            #pragma unroll
            for (int na = 0; na < 4; na++)
                #pragma unroll
                for (int i = 0; i < 4; i++) acc[na][i] = 0.f;

            #pragma unroll
            for (int ks = 0; ks < 5; ks++) {
                uint32_t ah[4], al[4];
                ldsm4(ah, aXt + ks * 32);
                ldsm4(al, aXt + ks * 32 + dXlo);
                #pragma unroll
                for (int np = 0; np < 2; np++) {
                    uint32_t ba = bW1_4 + (ks * 16 * W1S + np * 16) * 2;
                    uint32_t bh[4], bl[4];
                    ldsm4t(bh, ba);
                    ldsm4t(bl, ba + dW1lo);
                    mma_bf16(acc[2 * np],     ah, bh);
                    mma_bf16(acc[2 * np],     ah, bl);
                    mma_bf16(acc[2 * np],     al, bh);
                    mma_bf16(acc[2 * np + 1], ah, bh + 2);
                    mma_bf16(acc[2 * np + 1], ah, bl + 2);
                    mma_bf16(acc[2 * np + 1], al, bh + 2);
                }
            }

            // ---- epilogue: H = relu(acc + b1), split to bf16 hi/lo ----
            {
                int row0 = m_base + (lane >> 2);
                #pragma unroll
                for (int na = 0; na < 4; na++) {
                    int col = warp_n * 32 + na * 8 + (lane & 3) * 2;
                    float bb0 = sb1[col], bb1 = sb1[col + 1];
                    float f0 = fmaxf(acc[na][0] + bb0, 0.f);
                    float f1 = fmaxf(acc[na][1] + bb1, 0.f);
                    float f2 = fmaxf(acc[na][2] + bb0, 0.f);
                    float f3 = fmaxf(acc[na][3] + bb1, 0.f);
                    __nv_bfloat162 h01 = __floats2bfloat162_rn(f0, f1);
                    float2 hf01 = __bfloat1622float2(h01);
                    __nv_bfloat162 l01 = __floats2bfloat162_rn(f0 - hf01.x, f1 - hf01.y);
                    __nv_bfloat162 h23 = __floats2bfloat162_rn(f2, f3);
                    float2 hf23 = __bfloat1622float2(h23);
                    __nv_bfloat162 l23 = __floats2bfloat162_rn(f2 - hf23.x, f3 - hf23.y);
                    int o0 = (row0 * HS + col) * 2;
                    int o1 = ((row0 + 8) * HS + col) * 2;
                    *(uint32_t*)(smem + SM_HHI + o0) = *(uint32_t*)&h01;
                    *(uint32_t*)(smem + SM_HLO + o0) = *(uint32_t*)&l01;
                    *(uint32_t*)(smem + SM_HHI + o1) = *(uint32_t*)&h23;
                    *(uint32_t*)(smem + SM_HLO + o1) = *(uint32_t*)&l23;
                }
            }
            __syncthreads();

            // ---- GEMM2: yacc[t] += H(64x64) @ W2chunk(64x80), 3-term split ----
            float* ya = &yacc[t][0][0];
            #pragma unroll
            for (int ks = 0; ks < 4; ks++) {
                uint32_t ah[4], al[4];
                ldsm4(ah, aH + ks * 32);
                ldsm4(al, aH + ks * 32 + dHlo);
                #pragma unroll
                for (int np = 0; np < 2; np++) {
                    uint32_t ba = bW2_4 + (ks * 16 * W2S + np * 16) * 2;
                    uint32_t bh[4], bl[4];
                    ldsm4t(bh, ba);
                    ldsm4t(bl, ba + dW2lo);
                    mma_bf16(ya + (2 * np) * 4,     ah, bh);
                    mma_bf16(ya + (2 * np) * 4,     ah, bl);
                    mma_bf16(ya + (2 * np) * 4,     al, bh);
                    mma_bf16(ya + (2 * np + 1) * 4, ah, bh + 2);
                    mma_bf16(ya + (2 * np + 1) * 4, ah, bl + 2);
                    mma_bf16(ya + (2 * np + 1) * 4, al, bh + 2);
                }
                {
                    uint32_t ba = bW2_2 + (ks * 16 * W2S) * 2;
                    uint32_t bh[2], bl[2];
                    ldsm2t(bh, ba);
                    ldsm2t(bl, ba + dW2lo);
                    mma_bf16(ya + 16, ah, bh);
                    mma_bf16(ya + 16, ah, bl);
                    mma_bf16(ya + 16, al, bh);
                }
            }
            __syncthreads();   // H (and, after t=1, W tiles) free for reuse
        }
    }

    // ---- scatter: out[tok] += w * (y + b2)  (2 contributions/token) ----
    #pragma unroll
    for (int t = 0; t < 2; t++) {
        int row0 = t * 64 + m_base + (lane >> 2);
        int tk0 = stok[row0], tk1 = stok[row0 + 8];
        float w0 = swt[row0], w1v = swt[row0 + 8];
        float* o0 = out + (size_t)(tk0 < 0 ? 0 : tk0) * D;
        float* o1 = out + (size_t)(tk1 < 0 ? 0 : tk1) * D;
        #pragma unroll
        for (int na = 0; na < 5; na++) {
            int col = warp_n * 40 + na * 8 + (lane & 3) * 2;
            float b20 = sb2[col], b21 = sb2[col + 1];
            if (tk0 >= 0) {
                atomicAdd(&o0[col],     w0 * (yacc[t][na][0] + b20));
                atomicAdd(&o0[col + 1], w0 * (yacc[t][na][1] + b21));
            }
            if (tk1 >= 0) {
                atomicAdd(&o1[col],     w1v * (yacc[t][na][2] + b20));
                atomicAdd(&o1[col + 1], w1v * (yacc[t][na][3] + b21));
            }
        }
    }
}

// ---------------------------------------------------------------------------
extern "C" void kernel_launch(void* const* d_in, const int* in_sizes, int n_in,
                              void* d_out, int out_size) {
    const float* x  = (const float*)d_in[0];
    const float* Wg = (const float*)d_in[1];
    const float* bg = (const float*)d_in[2];
    const float* W1 = (const float*)d_in[3];
    const float* b1 = (const float*)d_in[4];
    const float* W2 = (const float*)d_in[5];
    const float* b2 = (const float*)d_in[6];
    float* out = (float*)d_out;

    int T = in_sizes[0] / D;

    cudaFuncSetAttribute(ffn_kernel, cudaFuncAttributeMaxDynamicSharedMemorySize, SMEM_TOTAL);

    void *cntp, *bufAp, *bufBp;
    cudaGetSymbolAddress(&cntp,  g_cnt);
    cudaGetSymbolAddress(&bufAp, g_bufA);
    cudaGetSymbolAddress(&bufBp, g_bufB);
    float* bufA = (float*)bufAp;
    float* bufB = (float*)bufBp;

    const int NPREP = E * D * HID + E * HID * D;   // 409600
    prep_kernel<<<(NPREP + 255) / 256, 256>>>(W1, W2);

    int  rb     = (T + RTB - 1) / RTB;
    int  chunks = (T + TBK - 1) / TBK;
    dim3 fgrid(chunks, E);

    const float* lin = x;
    for (int l = 0; l < NL; l++) {
        float* lout = (l == NL - 1) ? out : ((l & 1) ? bufB : bufA);
        cudaMemsetAsync(cntp, 0, sizeof(int) * E);
        // router zeroes lout and builds expert lists
        router_kernel<<<rb, RTB == 32 ? 128 : 128>>>(lin, Wg + (size_t)l * D * E, bg + l * E, lout, T);
        ffn_kernel<<<fgrid, 256, SMEM_TOTAL>>>(lin, lout, b1, b2);
        lin = lout;
    }
}

// round 7
// speedup vs baseline: 1.2210x; 1.2210x over previous
#include <cuda_runtime.h>
#include <cuda_bf16.h>
#include <math.h>
#include <stdint.h>

// Problem constants
#define D    80
#define E    8
#define HID  320
#define NL   4
#define TBK  64            // tokens per ffn block
#define NCK  5             // HID chunks of 64
#define MAXT 32768
#define RTB  128           // router tokens per block

// smem row strides (elements) — odd multiples of 8 -> conflict-free ldmatrix
#define XS   88
#define W1S  72
#define HS   72
#define W2S  88

// ffn smem layout (bytes)
#define SM_SB1   0                            // 320 floats
#define SM_SB2   1280                         // 80 floats
#define SM_SCNT  1600                         // 8 ints
#define SM_XHI   1664
#define SM_XLO   (SM_XHI  + TBK * XS * 2)     // 12928
#define SM_W1HI  (SM_XLO  + TBK * XS * 2)     // 24192
#define SM_W1LO  (SM_W1HI + 80 * W1S * 2)     // 35712
#define SM_W2HI  (SM_W1LO + 80 * W1S * 2)     // 47232
#define SM_W2LO  (SM_W2HI + 64 * W2S * 2)     // 58496
#define SM_HHI   (SM_W2LO + 64 * W2S * 2)     // 69760
#define SM_HLO   (SM_HHI  + 64 * HS * 2)      // 78976
#define SMEM_TOTAL (SM_HLO + 64 * HS * 2)     // 88192

// ---------------------------------------------------------------------------
// Scratch (no cudaMalloc allowed)
// ---------------------------------------------------------------------------
__device__ float    g_bufA[MAXT * D];           // combined activations
__device__ int      g_cnt[NL * E];              // per-layer expert counts
__device__ int      g_tok[E * MAXT];            // expert token lists
__device__ uint32_t g_sl [2 * MAXT];            // per-token (expert<<16)|slot
__device__ float    g_wtk[2 * MAXT];            // per-token top-2 weights
__device__ float    g_eo [2 * MAXT * D];        // expert outputs by global slot
// split-bf16 weights, natural layouts
__device__ __align__(16) unsigned short g_w1h[E * D * HID];   // [e][d][h]
__device__ __align__(16) unsigned short g_w1l[E * D * HID];
__device__ __align__(16) unsigned short g_w2h[E * HID * D];   // [e][h][d]
__device__ __align__(16) unsigned short g_w2l[E * HID * D];

// ---------------------------------------------------------------------------
// PTX helpers (sm_80-era: valid on compute_100 without the 'a' suffix)
// ---------------------------------------------------------------------------
__device__ __forceinline__ uint32_t smem_u32(const void* p) {
    uint32_t a;
    asm("{ .reg .u64 t; cvta.to.shared.u64 t, %1; cvt.u32.u64 %0, t; }" : "=r"(a) : "l"(p));
    return a;
}
__device__ __forceinline__ void ldsm4(uint32_t* r, uint32_t a) {
    asm volatile("ldmatrix.sync.aligned.m8n8.x4.shared.b16 {%0,%1,%2,%3}, [%4];"
        : "=r"(r[0]), "=r"(r[1]), "=r"(r[2]), "=r"(r[3]) : "r"(a));
}
__device__ __forceinline__ void ldsm4t(uint32_t* r, uint32_t a) {
    asm volatile("ldmatrix.sync.aligned.m8n8.x4.trans.shared.b16 {%0,%1,%2,%3}, [%4];"
        : "=r"(r[0]), "=r"(r[1]), "=r"(r[2]), "=r"(r[3]) : "r"(a));
}
__device__ __forceinline__ void ldsm2t(uint32_t* r, uint32_t a) {
    asm volatile("ldmatrix.sync.aligned.m8n8.x2.trans.shared.b16 {%0,%1}, [%2];"
        : "=r"(r[0]), "=r"(r[1]) : "r"(a));
}
__device__ __forceinline__ void mma_bf16(float* c, const uint32_t* a, const uint32_t* b) {
    asm volatile("mma.sync.aligned.m16n8k16.row.col.f32.bf16.bf16.f32 "
        "{%0,%1,%2,%3}, {%4,%5,%6,%7}, {%8,%9}, {%0,%1,%2,%3};"
        : "+f"(c[0]), "+f"(c[1]), "+f"(c[2]), "+f"(c[3])
        : "r"(a[0]), "r"(a[1]), "r"(a[2]), "r"(a[3]), "r"(b[0]), "r"(b[1]));
}
__device__ __forceinline__ void cpa16(uint32_t smem_dst, const void* gsrc) {
    asm volatile("cp.async.ca.shared.global [%0], [%1], 16;" :: "r"(smem_dst), "l"(gsrc));
}
#define CP_COMMIT() asm volatile("cp.async.commit_group;" ::: "memory")
#define CP_WAIT1()  asm volatile("cp.async.wait_group 1;" ::: "memory")
#define CP_WAIT0()  asm volatile("cp.async.wait_group 0;" ::: "memory")

// ---------------------------------------------------------------------------
// Init kernels
// ---------------------------------------------------------------------------
__global__ void zero_kernel() {
    if (threadIdx.x < NL * E) g_cnt[threadIdx.x] = 0;
}
__global__ void prep_kernel(const float* __restrict__ W1, const float* __restrict__ W2) {
    int i = blockIdx.x * blockDim.x + threadIdx.x;
    const int N1 = E * D * HID;
    const int N2 = E * HID * D;
    if (i < N1) {
        float v = W1[i];
        __nv_bfloat16 h = __float2bfloat16(v);
        __nv_bfloat16 l = __float2bfloat16(v - __bfloat162float(h));
        g_w1h[i] = *(unsigned short*)&h;
        g_w1l[i] = *(unsigned short*)&l;
    } else if (i < N1 + N2) {
        int j = i - N1;
        float v = W2[j];
        __nv_bfloat16 h = __float2bfloat16(v);
        __nv_bfloat16 l = __float2bfloat16(v - __bfloat162float(h));
        g_w2h[j] = *(unsigned short*)&h;
        g_w2l[j] = *(unsigned short*)&l;
    }
}

// ---------------------------------------------------------------------------
// Router: (optionally) combine previous layer's expert outputs per token
// (fixed-order 2-term sum -> deterministic), then (optionally) route.
// mode bit0 = combine (l>0), bit1 = route (l<NL).
// ---------------------------------------------------------------------------
__global__ void __launch_bounds__(RTB)
router_kernel(const float* __restrict__ xin,
              const int* __restrict__ cntPrev,
              int* __restrict__ cntCur,
              float* __restrict__ xout,
              const float* __restrict__ Wg,
              const float* __restrict__ bg,
              int T, int mode) {
    __shared__ float wg[D * E];
    __shared__ float bgs[E];
    __shared__ float xs[RTB * 81];
    __shared__ int   pfx[E];
    __shared__ int   lcnt[E], gbase[E];

    int tid  = threadIdx.x;
    int base = blockIdx.x * RTB;
    int ntok = T - base; if (ntok > RTB) ntok = RTB;
    if (ntok <= 0) return;
    bool doComb  = (mode & 1) != 0;
    bool doRoute = (mode & 2) != 0;

    if (doRoute) {
        for (int i = tid; i < D * E; i += RTB) wg[i] = Wg[i];
        if (tid < E) bgs[tid] = bg[tid];
    }
    if (tid < E) lcnt[tid] = 0;
    if (doComb && tid == 0) {
        int a = 0;
        for (int e = 0; e < E; e++) { pfx[e] = a; a += cntPrev[e]; }
    }
    __syncthreads();

    if (doComb) {
        // 4 threads per token: combine w0*eo0 + w1*eo1 -> xout (+ xs)
        #pragma unroll
        for (int pass = 0; pass < 4; pass++) {
            int r = pass * 32 + (tid >> 2);
            if (r < ntok) {
                int t = base + r;
                uint32_t s0 = g_sl[2 * t], s1 = g_sl[2 * t + 1];
                float w0 = g_wtk[2 * t], w1 = g_wtk[2 * t + 1];
                const float* r0 = g_eo + (size_t)(pfx[s0 >> 16] + (int)(s0 & 0xFFFF)) * D;
                const float* r1 = g_eo + (size_t)(pfx[s1 >> 16] + (int)(s1 & 0xFFFF)) * D;
                float* xo = xout + (size_t)t * D;
                int sub = tid & 3;
                #pragma unroll
                for (int j = 0; j < 5; j++) {
                    int c = sub * 4 + j * 16;
                    float4 a = *(const float4*)&r0[c];
                    float4 b = *(const float4*)&r1[c];
                    float4 v;
                    v.x = w0 * a.x + w1 * b.x;
                    v.y = w0 * a.y + w1 * b.y;
                    v.z = w0 * a.z + w1 * b.z;
                    v.w = w0 * a.w + w1 * b.w;
                    *(float4*)&xo[c] = v;
                    float* dst = &xs[r * 81 + c];
                    dst[0] = v.x; dst[1] = v.y; dst[2] = v.z; dst[3] = v.w;
                }
            }
        }
    } else {
        // layer 0: stage from xin (coalesced)
        const float4* gx = (const float4*)(xin + (size_t)base * D);
        int n4 = ntok * (D / 4);
        for (int i = tid; i < n4; i += RTB) {
            float4 v = gx[i];
            int r = i / 20, c = (i - r * 20) * 4;
            float* dst = &xs[r * 81 + c];
            dst[0] = v.x; dst[1] = v.y; dst[2] = v.z; dst[3] = v.w;
        }
    }
    __syncthreads();

    if (!doRoute) return;

    int   i0 = 0, i1 = 0, lp0 = 0, lp1 = 0;
    float v0 = -INFINITY, v1 = -INFINITY;
    if (tid < ntok) {
        float acc[E];
        #pragma unroll
        for (int e = 0; e < E; e++) acc[e] = bgs[e];
        const float* xr = &xs[tid * 81];
        #pragma unroll 4
        for (int k = 0; k < D; k++) {
            float xv = xr[k];
            #pragma unroll
            for (int e = 0; e < E; e++) acc[e] = fmaf(xv, wg[k * E + e], acc[e]);
        }
        #pragma unroll
        for (int e = 0; e < E; e++) {
            float v = acc[e];
            if (v > v0)      { v1 = v0; i1 = i0; v0 = v; i0 = e; }
            else if (v > v1) { v1 = v;  i1 = e; }
        }
        lp0 = atomicAdd(&lcnt[i0], 1);
        lp1 = atomicAdd(&lcnt[i1], 1);
    }
    __syncthreads();
    if (tid < E) gbase[tid] = atomicAdd(&cntCur[tid], lcnt[tid]);
    __syncthreads();
    if (tid < ntok) {
        int t = base + tid;
        int slot0 = gbase[i0] + lp0;
        int slot1 = gbase[i1] + lp1;
        g_tok[i0 * MAXT + slot0] = t;
        g_tok[i1 * MAXT + slot1] = t;
        g_sl[2 * t]     = ((uint32_t)i0 << 16) | (uint32_t)slot0;
        g_sl[2 * t + 1] = ((uint32_t)i1 << 16) | (uint32_t)slot1;
        g_wtk[2 * t]     = v0;
        g_wtk[2 * t + 1] = v1;
    }
}

// ---------------------------------------------------------------------------
// FFN: compact 1-D grid; 64 tokens of one expert per block.
// split-bf16 mma.sync GEMMs, cp.async-pipelined weight tiles,
// non-atomic STG of expert-output rows (y + b2) into g_eo slots.
// ---------------------------------------------------------------------------
__global__ void __launch_bounds__(256, 2)
ffn_kernel(const float* __restrict__ in,
           const int* __restrict__ cnt,
           const float* __restrict__ b1,  const float* __restrict__ b2) {
    extern __shared__ char smem[];
    uint32_t sb = smem_u32(smem);
    int tid  = threadIdx.x;
    int lane = tid & 31;
    int wid  = tid >> 5;

    int* scnt = (int*)(smem + SM_SCNT);
    float* sb1a = (float*)(smem + SM_SB1);
    float* sb2  = (float*)(smem + SM_SB2);

    if (tid < E) scnt[tid] = cnt[tid];
    __syncthreads();

    // block -> (expert, start, slot prefix base)
    int b = blockIdx.x;
    int e = -1, start = 0, pbase = 0, n = 0;
    {
        int accB = 0, accN = 0;
        #pragma unroll
        for (int ee = 0; ee < E; ee++) {
            int ne = scnt[ee];
            int bl = (ne + TBK - 1) >> 6;
            if (e < 0 && b < accB + bl) { e = ee; start = (b - accB) * TBK; pbase = accN; n = ne; }
            accB += bl; accN += ne;
        }
    }
    if (e < 0) return;

    // ---- gather X, split into bf16 hi/lo smem (2 threads per token) ----
    if (tid < 2 * TBK) {
        int r = tid >> 1, half = tid & 1;
        int tk = (start + r < n) ? g_tok[e * MAXT + start + r] : -1;
        const float* xr = in + (size_t)(tk < 0 ? 0 : tk) * D + half * 40;
        char* dh = smem + SM_XHI + (r * XS + half * 40) * 2;
        char* dl = smem + SM_XLO + (r * XS + half * 40) * 2;
        #pragma unroll
        for (int j = 0; j < 20; j++) {
            float2 v = (tk >= 0) ? *(const float2*)&xr[2 * j] : make_float2(0.f, 0.f);
            __nv_bfloat162 h2 = __floats2bfloat162_rn(v.x, v.y);
            float2 hf = __bfloat1622float2(h2);
            __nv_bfloat162 l2 = __floats2bfloat162_rn(v.x - hf.x, v.y - hf.y);
            *(uint32_t*)(dh + 4 * j) = *(uint32_t*)&h2;
            *(uint32_t*)(dl + 4 * j) = *(uint32_t*)&l2;
        }
    }
    // stage biases
    for (int i = tid; i < HID; i += 256) sb1a[i] = b1[e * HID + i];
    if (tid < D) sb2[tid] = b2[e * D + tid];

    const unsigned short* w1hB = g_w1h + e * D * HID;
    const unsigned short* w1lB = g_w1l + e * D * HID;
    const unsigned short* w2hB = g_w2h + e * HID * D;
    const unsigned short* w2lB = g_w2l + e * HID * D;

    // ---- cp.async weight-tile staging helpers ----
    // W1 chunk: 80 rows x 64 cols (hi+lo), 640 x 16B each
    // W2 chunk: 64 rows x 80 cols (hi+lo), 640 x 16B each
    #define ISSUE_W1(c) { \
        int idx0 = tid;       { int row = idx0 >> 3, v = idx0 & 7; \
            cpa16(sb + SM_W1HI + (row * W1S + v * 8) * 2, w1hB + (c) * 64 + row * HID + v * 8); \
            cpa16(sb + SM_W1LO + (row * W1S + v * 8) * 2, w1lB + (c) * 64 + row * HID + v * 8); } \
        int idx1 = tid + 256; { int row = idx1 >> 3, v = idx1 & 7; \
            cpa16(sb + SM_W1HI + (row * W1S + v * 8) * 2, w1hB + (c) * 64 + row * HID + v * 8); \
            cpa16(sb + SM_W1LO + (row * W1S + v * 8) * 2, w1lB + (c) * 64 + row * HID + v * 8); } \
        if (tid < 128) { int idx2 = tid + 512; int row = idx2 >> 3, v = idx2 & 7; \
            cpa16(sb + SM_W1HI + (row * W1S + v * 8) * 2, w1hB + (c) * 64 + row * HID + v * 8); \
            cpa16(sb + SM_W1LO + (row * W1S + v * 8) * 2, w1lB + (c) * 64 + row * HID + v * 8); } }
    #define ISSUE_W2(c) { \
        int idx0 = tid;       { int row = idx0 / 10, v = idx0 - row * 10; \
            cpa16(sb + SM_W2HI + (row * W2S + v * 8) * 2, w2hB + (c) * 64 * D + row * D + v * 8); \
            cpa16(sb + SM_W2LO + (row * W2S + v * 8) * 2, w2lB + (c) * 64 * D + row * D + v * 8); } \
        int idx1 = tid + 256; { int row = idx1 / 10, v = idx1 - row * 10; \
            cpa16(sb + SM_W2HI + (row * W2S + v * 8) * 2, w2hB + (c) * 64 * D + row * D + v * 8); \
            cpa16(sb + SM_W2LO + (row * W2S + v * 8) * 2, w2lB + (c) * 64 * D + row * D + v * 8); } \
        if (tid < 128) { int idx2 = tid + 512; int row = idx2 / 10, v = idx2 - row * 10; \
            cpa16(sb + SM_W2HI + (row * W2S + v * 8) * 2, w2hB + (c) * 64 * D + row * D + v * 8); \
            cpa16(sb + SM_W2LO + (row * W2S + v * 8) * 2, w2lB + (c) * 64 * D + row * D + v * 8); } }

    ISSUE_W1(0); CP_COMMIT();
    ISSUE_W2(0); CP_COMMIT();

    // warp tiling: 4 (M) x 2 (N)
    int warp_m = wid >> 1;
    int warp_n = wid & 1;
    int m_base = warp_m * 16;

    uint32_t aX    = sb + SM_XHI  + ((m_base + (lane & 15)) * XS + (lane >> 4) * 8) * 2;
    uint32_t aH    = sb + SM_HHI  + ((m_base + (lane & 15)) * HS + (lane >> 4) * 8) * 2;
    uint32_t bW1_4 = sb + SM_W1HI + ((lane & 15) * W1S + warp_n * 32 + (lane >> 4) * 8) * 2;
    uint32_t bW2_4 = sb + SM_W2HI + ((lane & 15) * W2S + warp_n * 40 + (lane >> 4) * 8) * 2;
    uint32_t bW2_2 = sb + SM_W2HI + ((lane & 15) * W2S + warp_n * 40 + 32) * 2;
    const int dXlo  = SM_XLO  - SM_XHI;
    const int dW1lo = SM_W1LO - SM_W1HI;
    const int dHlo  = SM_HLO  - SM_HHI;
    const int dW2lo = SM_W2LO - SM_W2HI;

    float yacc[5][4];
    #pragma unroll
    for (int na = 0; na < 5; na++)
        #pragma unroll
        for (int i = 0; i < 4; i++) yacc[na][i] = 0.f;

    #pragma unroll
    for (int c = 0; c < NCK; c++) {
        CP_WAIT1();          // W1[c] ready (W2[c] may still be in flight)
        __syncthreads();

        // ---- GEMM1: acc = X(64x80) @ W1chunk(80x64), 3-term split ----
        float acc[4][4];
        #pragma unroll
        for (int na = 0; na < 4; na++)
            #pragma unroll
            for (int i = 0; i < 4; i++) acc[na][i] = 0.f;

        #pragma unroll
        for (int ks = 0; ks < 5; ks++) {
            uint32_t ah[4], al[4];
            ldsm4(ah, aX + ks * 32);
            ldsm4(al, aX + ks * 32 + dXlo);
            #pragma unroll
            for (int np = 0; np < 2; np++) {
                uint32_t ba = bW1_4 + (ks * 16 * W1S + np * 16) * 2;
                uint32_t bh[4], bl[4];
                ldsm4t(bh, ba);
                ldsm4t(bl, ba + dW1lo);
                mma_bf16(acc[2 * np],     ah, bh);
                mma_bf16(acc[2 * np],     ah, bl);
                mma_bf16(acc[2 * np],     al, bh);
                mma_bf16(acc[2 * np + 1], ah, bh + 2);
                mma_bf16(acc[2 * np + 1], ah, bl + 2);
                mma_bf16(acc[2 * np + 1], al, bh + 2);
            }
        }

        // ---- epilogue: H = relu(acc + b1), split to bf16 hi/lo ----
        {
            int row0 = m_base + (lane >> 2);
            #pragma unroll
            for (int na = 0; na < 4; na++) {
                int col = warp_n * 32 + na * 8 + (lane & 3) * 2;
                float bb0 = sb1a[c * 64 + col], bb1 = sb1a[c * 64 + col + 1];
                float f0 = fmaxf(acc[na][0] + bb0, 0.f);
                float f1 = fmaxf(acc[na][1] + bb1, 0.f);
                float f2 = fmaxf(acc[na][2] + bb0, 0.f);
                float f3 = fmaxf(acc[na][3] + bb1, 0.f);
                __nv_bfloat162 h01 = __floats2bfloat162_rn(f0, f1);
                float2 hf01 = __bfloat1622float2(h01);
                __nv_bfloat162 l01 = __floats2bfloat162_rn(f0 - hf01.x, f1 - hf01.y);
                __nv_bfloat162 h23 = __floats2bfloat162_rn(f2, f3);
                float2 hf23 = __bfloat1622float2(h23);
                __nv_bfloat162 l23 = __floats2bfloat162_rn(f2 - hf23.x, f3 - hf23.y);
                int o0 = (row0 * HS + col) * 2;
                int o1 = ((row0 + 8) * HS + col) * 2;
                *(uint32_t*)(smem + SM_HHI + o0) = *(uint32_t*)&h01;
                *(uint32_t*)(smem + SM_HLO + o0) = *(uint32_t*)&l01;
                *(uint32_t*)(smem + SM_HHI + o1) = *(uint32_t*)&h23;
                *(uint32_t*)(smem + SM_HLO + o1) = *(uint32_t*)&l23;
            }
        }
        __syncthreads();     // H visible; W1 buffer free

        if (c < NCK - 1) { ISSUE_W1(c + 1); CP_COMMIT(); CP_WAIT1(); }
        else             { CP_WAIT0(); }
        __syncthreads();     // W2[c] visible

        // ---- GEMM2: yacc += H(64x64) @ W2chunk(64x80), 3-term split ----
        #pragma unroll
        for (int ks = 0; ks < 4; ks++) {
            uint32_t ah[4], al[4];
            ldsm4(ah, aH + ks * 32);
            ldsm4(al, aH + ks * 32 + dHlo);
            #pragma unroll
            for (int np = 0; np < 2; np++) {
                uint32_t ba = bW2_4 + (ks * 16 * W2S + np * 16) * 2;
                uint32_t bh[4], bl[4];
                ldsm4t(bh, ba);
                ldsm4t(bl, ba + dW2lo);
                mma_bf16(yacc[2 * np],     ah, bh);
                mma_bf16(yacc[2 * np],     ah, bl);
                mma_bf16(yacc[2 * np],     al, bh);
                mma_bf16(yacc[2 * np + 1], ah, bh + 2);
                mma_bf16(yacc[2 * np + 1], ah, bl + 2);
                mma_bf16(yacc[2 * np + 1], al, bh + 2);
            }
            {
                uint32_t ba = bW2_2 + (ks * 16 * W2S) * 2;
                uint32_t bh[2], bl[2];
                ldsm2t(bh, ba);
                ldsm2t(bl, ba + dW2lo);
                mma_bf16(yacc[4], ah, bh);
                mma_bf16(yacc[4], ah, bl);
                mma_bf16(yacc[4], al, bh);
            }
        }
        __syncthreads();     // W2 buffer + H free

        if (c < NCK - 1) { ISSUE_W2(c + 1); CP_COMMIT(); }
    }

    // ---- write expert-output rows (y + b2) to slot buffer, non-atomic ----
    {
        int row0 = m_base + (lane >> 2);
        int row1 = row0 + 8;
        bool v0 = (start + row0 < n);
        bool v1 = (start + row1 < n);
        float* o0 = g_eo + (size_t)(pbase + start + row0) * D;
        float* o1 = g_eo + (size_t)(pbase + start + row1) * D;
        #pragma unroll
        for (int na = 0; na < 5; na++) {
            int col = warp_n * 40 + na * 8 + (lane & 3) * 2;
            float b20 = sb2[col], b21 = sb2[col + 1];
            if (v0) *(float2*)&o0[col] = make_float2(yacc[na][0] + b20, yacc[na][1] + b21);
            if (v1) *(float2*)&o1[col] = make_float2(yacc[na][2] + b20, yacc[na][3] + b21);
        }
    }
    #undef ISSUE_W1
    #undef ISSUE_W2
}

// ---------------------------------------------------------------------------
extern "C" void kernel_launch(void* const* d_in, const int* in_sizes, int n_in,
                              void* d_out, int out_size) {
    const float* x  = (const float*)d_in[0];
    const float* Wg = (const float*)d_in[1];
    const float* bg = (const float*)d_in[2];
    const float* W1 = (const float*)d_in[3];
    const float* b1 = (const float*)d_in[4];
    const float* W2 = (const float*)d_in[5];
    const float* b2 = (const float*)d_in[6];
    float* out = (float*)d_out;

    int T = in_sizes[0] / D;

    cudaFuncSetAttribute(ffn_kernel, cudaFuncAttributeMaxDynamicSharedMemorySize, SMEM_TOTAL);

    void *cntp, *bufAp;
    cudaGetSymbolAddress(&cntp,  g_cnt);
    cudaGetSymbolAddress(&bufAp, g_bufA);
    int*   cntb = (int*)cntp;
    float* bufA = (float*)bufAp;

    const int NPREP = E * D * HID + E * HID * D;   // 409600
    prep_kernel<<<(NPREP + 255) / 256, 256>>>(W1, W2);
    zero_kernel<<<1, 64>>>();

    int rb = (T + RTB - 1) / RTB;
    int GB = (2 * T) / TBK + E + 1;   // compact ffn grid upper bound

    for (int l = 0; l < NL; l++) {
        int mode = (l == 0) ? 2 : 3;
        router_kernel<<<rb, RTB>>>((l == 0) ? x : nullptr,
                                   cntb + (l - 1) * E,
                                   cntb + l * E,
                                   bufA,
                                   Wg + (size_t)l * D * E, bg + l * E,
                                   T, mode);
        ffn_kernel<<<GB, 256, SMEM_TOTAL>>>((l == 0) ? x : bufA,
                                            cntb + l * E, b1, b2);
    }
    // final combine-only pass -> d_out
    router_kernel<<<rb, RTB>>>(nullptr, cntb + (NL - 1) * E, cntb, out,
                               Wg, bg, T, 1);
}

// round 8
// speedup vs baseline: 1.4136x; 1.1578x over previous
#include <cuda_runtime.h>
#include <cuda_bf16.h>
#include <math.h>
#include <stdint.h>

// Problem constants
#define D    80
#define E    8
#define HID  320
#define NL   4
#define TBK  128           // tokens per ffn block
#define NCK  5             // HID chunks of 64
#define MAXT 32768
#define RTB  128           // router tokens per block

// smem row strides (elements) — odd multiples of 8 -> conflict-free ldmatrix
#define XS   88
#define W1S  72
#define W2S  88

// ffn smem layout (bytes)
#define SM_SB1   0                            // 320 floats
#define SM_SB2   1280                         // 80 floats
#define SM_SCNT  1600                         // 8 ints
#define SM_XHI   1664
#define SM_XLO   (SM_XHI  + TBK * XS * 2)     // +22528 = 24192
#define SM_W1HI  (SM_XLO  + TBK * XS * 2)     // 46720
#define SM_W1LO  (SM_W1HI + 80 * W1S * 2)     // 58240
#define SM_W2HI  (SM_W1LO + 80 * W1S * 2)     // 69760
#define SM_W2LO  (SM_W2HI + 64 * W2S * 2)     // 81024
#define SMEM_TOTAL (SM_W2LO + 64 * W2S * 2)   // 92288

// ---------------------------------------------------------------------------
// Scratch (no cudaMalloc allowed)
// ---------------------------------------------------------------------------
__device__ float    g_bufA[MAXT * D];           // combined activations
__device__ int      g_cnt[NL * E];              // per-layer expert counts
__device__ int      g_tok[E * MAXT];            // expert token lists
__device__ uint32_t g_sl [2 * MAXT];            // per-token (expert<<16)|slot
__device__ float    g_wtk[2 * MAXT];            // per-token top-2 weights
__device__ float    g_eo [2 * MAXT * D];        // expert outputs by global slot
// split-bf16 weights, natural layouts
__device__ __align__(16) unsigned short g_w1h[E * D * HID];   // [e][d][h]
__device__ __align__(16) unsigned short g_w1l[E * D * HID];
__device__ __align__(16) unsigned short g_w2h[E * HID * D];   // [e][h][d]
__device__ __align__(16) unsigned short g_w2l[E * HID * D];

// ---------------------------------------------------------------------------
// PTX helpers
// ---------------------------------------------------------------------------
__device__ __forceinline__ uint32_t smem_u32(const void* p) {
    uint32_t a;
    asm("{ .reg .u64 t; cvta.to.shared.u64 t, %1; cvt.u32.u64 %0, t; }" : "=r"(a) : "l"(p));
    return a;
}
__device__ __forceinline__ void ldsm4(uint32_t* r, uint32_t a) {
    asm volatile("ldmatrix.sync.aligned.m8n8.x4.shared.b16 {%0,%1,%2,%3}, [%4];"
        : "=r"(r[0]), "=r"(r[1]), "=r"(r[2]), "=r"(r[3]) : "r"(a));
}
__device__ __forceinline__ void ldsm4t(uint32_t* r, uint32_t a) {
    asm volatile("ldmatrix.sync.aligned.m8n8.x4.trans.shared.b16 {%0,%1,%2,%3}, [%4];"
        : "=r"(r[0]), "=r"(r[1]), "=r"(r[2]), "=r"(r[3]) : "r"(a));
}
__device__ __forceinline__ void mma_bf16(float* c, const uint32_t* a, const uint32_t* b) {
    asm volatile("mma.sync.aligned.m16n8k16.row.col.f32.bf16.bf16.f32 "
        "{%0,%1,%2,%3}, {%4,%5,%6,%7}, {%8,%9}, {%0,%1,%2,%3};"
        : "+f"(c[0]), "+f"(c[1]), "+f"(c[2]), "+f"(c[3])
        : "r"(a[0]), "r"(a[1]), "r"(a[2]), "r"(a[3]), "r"(b[0]), "r"(b[1]));
}
__device__ __forceinline__ void cpa16(uint32_t smem_dst, const void* gsrc) {
    asm volatile("cp.async.ca.shared.global [%0], [%1], 16;" :: "r"(smem_dst), "l"(gsrc));
}
#define CP_COMMIT() asm volatile("cp.async.commit_group;" ::: "memory")
#define CP_WAIT1()  asm volatile("cp.async.wait_group 1;" ::: "memory")
#define CP_WAIT0()  asm volatile("cp.async.wait_group 0;" ::: "memory")

// ---------------------------------------------------------------------------
// Init kernels
// ---------------------------------------------------------------------------
__global__ void zero_kernel() {
    if (threadIdx.x < NL * E) g_cnt[threadIdx.x] = 0;
}
__global__ void prep_kernel(const float* __restrict__ W1, const float* __restrict__ W2) {
    int i = blockIdx.x * blockDim.x + threadIdx.x;
    const int N1 = E * D * HID;
    const int N2 = E * HID * D;
    if (i < N1) {
        float v = W1[i];
        __nv_bfloat16 h = __float2bfloat16(v);
        __nv_bfloat16 l = __float2bfloat16(v - __bfloat162float(h));
        g_w1h[i] = *(unsigned short*)&h;
        g_w1l[i] = *(unsigned short*)&l;
    } else if (i < N1 + N2) {
        int j = i - N1;
        float v = W2[j];
        __nv_bfloat16 h = __float2bfloat16(v);
        __nv_bfloat16 l = __float2bfloat16(v - __bfloat162float(h));
        g_w2h[j] = *(unsigned short*)&h;
        g_w2l[j] = *(unsigned short*)&l;
    }
}

// ---------------------------------------------------------------------------
// Router: (optionally) combine previous layer's expert outputs per token
// (fixed-order 2-term sum -> deterministic), then (optionally) route.
// mode bit0 = combine (l>0), bit1 = route (l<NL).
// ---------------------------------------------------------------------------
__global__ void __launch_bounds__(RTB)
router_kernel(const float* __restrict__ xin,
              const int* __restrict__ cntPrev,
              int* __restrict__ cntCur,
              float* __restrict__ xout,
              const float* __restrict__ Wg,
              const float* __restrict__ bg,
              int T, int mode) {
    __shared__ float wg[D * E];
    __shared__ float bgs[E];
    __shared__ float xs[RTB * 81];
    __shared__ int   pfx[E];
    __shared__ int   lcnt[E], gbase[E];

    int tid  = threadIdx.x;
    int base = blockIdx.x * RTB;
    int ntok = T - base; if (ntok > RTB) ntok = RTB;
    if (ntok <= 0) return;
    bool doComb  = (mode & 1) != 0;
    bool doRoute = (mode & 2) != 0;

    if (doRoute) {
        for (int i = tid; i < D * E; i += RTB) wg[i] = Wg[i];
        if (tid < E) bgs[tid] = bg[tid];
    }
    if (tid < E) lcnt[tid] = 0;
    if (doComb && tid == 0) {
        int a = 0;
        for (int e = 0; e < E; e++) { pfx[e] = a; a += cntPrev[e]; }
    }
    __syncthreads();

    if (doComb) {
        #pragma unroll
        for (int pass = 0; pass < 4; pass++) {
            int r = pass * 32 + (tid >> 2);
            if (r < ntok) {
                int t = base + r;
                uint32_t s0 = g_sl[2 * t], s1 = g_sl[2 * t + 1];
                float w0 = g_wtk[2 * t], w1 = g_wtk[2 * t + 1];
                const float* r0 = g_eo + (size_t)(pfx[s0 >> 16] + (int)(s0 & 0xFFFF)) * D;
                const float* r1 = g_eo + (size_t)(pfx[s1 >> 16] + (int)(s1 & 0xFFFF)) * D;
                float* xo = xout + (size_t)t * D;
                int sub = tid & 3;
                #pragma unroll
                for (int j = 0; j < 5; j++) {
                    int c = sub * 4 + j * 16;
                    float4 a = *(const float4*)&r0[c];
                    float4 b = *(const float4*)&r1[c];
                    float4 v;
                    v.x = w0 * a.x + w1 * b.x;
                    v.y = w0 * a.y + w1 * b.y;
                    v.z = w0 * a.z + w1 * b.z;
                    v.w = w0 * a.w + w1 * b.w;
                    *(float4*)&xo[c] = v;
                    float* dst = &xs[r * 81 + c];
                    dst[0] = v.x; dst[1] = v.y; dst[2] = v.z; dst[3] = v.w;
                }
            }
        }
    } else {
        const float4* gx = (const float4*)(xin + (size_t)base * D);
        int n4 = ntok * (D / 4);
        for (int i = tid; i < n4; i += RTB) {
            float4 v = gx[i];
            int r = i / 20, c = (i - r * 20) * 4;
            float* dst = &xs[r * 81 + c];
            dst[0] = v.x; dst[1] = v.y; dst[2] = v.z; dst[3] = v.w;
        }
    }
    __syncthreads();

    if (!doRoute) return;

    int   i0 = 0, i1 = 0, lp0 = 0, lp1 = 0;
    float v0 = -INFINITY, v1 = -INFINITY;
    if (tid < ntok) {
        float acc[E];
        #pragma unroll
        for (int e = 0; e < E; e++) acc[e] = bgs[e];
        const float* xr = &xs[tid * 81];
        #pragma unroll 4
        for (int k = 0; k < D; k++) {
            float xv = xr[k];
            #pragma unroll
            for (int e = 0; e < E; e++) acc[e] = fmaf(xv, wg[k * E + e], acc[e]);
        }
        #pragma unroll
        for (int e = 0; e < E; e++) {
            float v = acc[e];
            if (v > v0)      { v1 = v0; i1 = i0; v0 = v; i0 = e; }
            else if (v > v1) { v1 = v;  i1 = e; }
        }
        lp0 = atomicAdd(&lcnt[i0], 1);
        lp1 = atomicAdd(&lcnt[i1], 1);
    }
    __syncthreads();
    if (tid < E) gbase[tid] = atomicAdd(&cntCur[tid], lcnt[tid]);
    __syncthreads();
    if (tid < ntok) {
        int t = base + tid;
        int slot0 = gbase[i0] + lp0;
        int slot1 = gbase[i1] + lp1;
        g_tok[i0 * MAXT + slot0] = t;
        g_tok[i1 * MAXT + slot1] = t;
        g_sl[2 * t]     = ((uint32_t)i0 << 16) | (uint32_t)slot0;
        g_sl[2 * t + 1] = ((uint32_t)i1 << 16) | (uint32_t)slot1;
        g_wtk[2 * t]     = v0;
        g_wtk[2 * t + 1] = v1;
    }
}

// ---------------------------------------------------------------------------
// FFN: 128 tokens of one expert per block; 8 warps, each warp owns 16 M-rows
// and the FULL N. GEMM1 C-fragments are converted (bias+relu+split-bf16) in
// registers directly into GEMM2 A-fragments (FlashAttention layout reuse):
// H never touches shared memory.
// ---------------------------------------------------------------------------
__global__ void __launch_bounds__(256, 2)
ffn_kernel(const float* __restrict__ in,
           const int* __restrict__ cnt,
           const float* __restrict__ b1,  const float* __restrict__ b2) {
    extern __shared__ char smem[];
    uint32_t sb = smem_u32(smem);
    int tid  = threadIdx.x;
    int lane = tid & 31;
    int wid  = tid >> 5;

    int*   scnt = (int*)(smem + SM_SCNT);
    float* sb1a = (float*)(smem + SM_SB1);
    float* sb2  = (float*)(smem + SM_SB2);

    if (tid < E) scnt[tid] = cnt[tid];
    __syncthreads();

    // block -> (expert, start, slot prefix base)
    int b = blockIdx.x;
    int e = -1, start = 0, pbase = 0, n = 0;
    {
        int accB = 0, accN = 0;
        #pragma unroll
        for (int ee = 0; ee < E; ee++) {
            int ne = scnt[ee];
            int bl = (ne + TBK - 1) >> 7;
            if (e < 0 && b < accB + bl) { e = ee; start = (b - accB) * TBK; pbase = accN; n = ne; }
            accB += bl; accN += ne;
        }
    }
    if (e < 0) return;

    // ---- gather X, split into bf16 hi/lo smem (2 threads per token) ----
    {
        int r = tid >> 1, half = tid & 1;
        int tk = (start + r < n) ? g_tok[e * MAXT + start + r] : -1;
        const float* xr = in + (size_t)(tk < 0 ? 0 : tk) * D + half * 40;
        char* dh = smem + SM_XHI + (r * XS + half * 40) * 2;
        char* dl = smem + SM_XLO + (r * XS + half * 40) * 2;
        #pragma unroll
        for (int j = 0; j < 20; j++) {
            float2 v = (tk >= 0) ? *(const float2*)&xr[2 * j] : make_float2(0.f, 0.f);
            __nv_bfloat162 h2 = __floats2bfloat162_rn(v.x, v.y);
            float2 hf = __bfloat1622float2(h2);
            __nv_bfloat162 l2 = __floats2bfloat162_rn(v.x - hf.x, v.y - hf.y);
            *(uint32_t*)(dh + 4 * j) = *(uint32_t*)&h2;
            *(uint32_t*)(dl + 4 * j) = *(uint32_t*)&l2;
        }
    }
    for (int i = tid; i < HID; i += 256) sb1a[i] = b1[e * HID + i];
    if (tid < D) sb2[tid] = b2[e * D + tid];

    const unsigned short* w1hB = g_w1h + e * D * HID;
    const unsigned short* w1lB = g_w1l + e * D * HID;
    const unsigned short* w2hB = g_w2h + e * HID * D;
    const unsigned short* w2lB = g_w2l + e * HID * D;

    // cp.async weight staging (W1: 80x64 hi+lo; W2: 64x80 hi+lo; 640x16B each)
    #define ISSUE_W1(c) { \
        int idx0 = tid;       { int row = idx0 >> 3, v = idx0 & 7; \
            cpa16(sb + SM_W1HI + (row * W1S + v * 8) * 2, w1hB + (c) * 64 + row * HID + v * 8); \
            cpa16(sb + SM_W1LO + (row * W1S + v * 8) * 2, w1lB + (c) * 64 + row * HID + v * 8); } \
        int idx1 = tid + 256; { int row = idx1 >> 3, v = idx1 & 7; \
            cpa16(sb + SM_W1HI + (row * W1S + v * 8) * 2, w1hB + (c) * 64 + row * HID + v * 8); \
            cpa16(sb + SM_W1LO + (row * W1S + v * 8) * 2, w1lB + (c) * 64 + row * HID + v * 8); } \
        if (tid < 128) { int idx2 = tid + 512; int row = idx2 >> 3, v = idx2 & 7; \
            cpa16(sb + SM_W1HI + (row * W1S + v * 8) * 2, w1hB + (c) * 64 + row * HID + v * 8); \
            cpa16(sb + SM_W1LO + (row * W1S + v * 8) * 2, w1lB + (c) * 64 + row * HID + v * 8); } }
    #define ISSUE_W2(c) { \
        int idx0 = tid;       { int row = idx0 / 10, v = idx0 - row * 10; \
            cpa16(sb + SM_W2HI + (row * W2S + v * 8) * 2, w2hB + (c) * 64 * D + row * D + v * 8); \
            cpa16(sb + SM_W2LO + (row * W2S + v * 8) * 2, w2lB + (c) * 64 * D + row * D + v * 8); } \
        int idx1 = tid + 256; { int row = idx1 / 10, v = idx1 - row * 10; \
            cpa16(sb + SM_W2HI + (row * W2S + v * 8) * 2, w2hB + (c) * 64 * D + row * D + v * 8); \
            cpa16(sb + SM_W2LO + (row * W2S + v * 8) * 2, w2lB + (c) * 64 * D + row * D + v * 8); } \
        if (tid < 128) { int idx2 = tid + 512; int row = idx2 / 10, v = idx2 - row * 10; \
            cpa16(sb + SM_W2HI + (row * W2S + v * 8) * 2, w2hB + (c) * 64 * D + row * D + v * 8); \
            cpa16(sb + SM_W2LO + (row * W2S + v * 8) * 2, w2lB + (c) * 64 * D + row * D + v * 8); } }

    ISSUE_W1(0); CP_COMMIT();   // group A0
    ISSUE_W2(0); CP_COMMIT();   // group B0

    // warp owns rows [16*wid, 16*wid+16)
    uint32_t aX  = sb + SM_XHI  + (((wid << 4) + (lane & 15)) * XS + (lane >> 4) * 8) * 2;
    uint32_t bW1 = sb + SM_W1HI + ((lane & 15) * W1S + (lane >> 4) * 8) * 2;
    uint32_t bW2 = sb + SM_W2HI + ((lane & 15) * W2S + (lane >> 4) * 8) * 2;
    const int dXlo  = SM_XLO  - SM_XHI;
    const int dW1lo = SM_W1LO - SM_W1HI;
    const int dW2lo = SM_W2LO - SM_W2HI;

    // GEMM2 accumulators: 10 n8-atoms (80 cols) x 4
    float yacc[10][4];
    #pragma unroll
    for (int na = 0; na < 10; na++)
        #pragma unroll
        for (int i = 0; i < 4; i++) yacc[na][i] = 0.f;

    int bcol = (lane & 3) * 2;   // fragment col offset within n8 atom

    #pragma unroll
    for (int c = 0; c < NCK; c++) {
        CP_WAIT1();          // W1[c] done (this thread), W2[c] may be pending
        __syncthreads();     // W1[c] visible block-wide

        // ---- GEMM1: acc = X(16x80) @ W1chunk(80x64), 3-term split ----
        float acc[8][4];
        #pragma unroll
        for (int na = 0; na < 8; na++)
            #pragma unroll
            for (int i = 0; i < 4; i++) acc[na][i] = 0.f;

        #pragma unroll
        for (int ks = 0; ks < 5; ks++) {
            uint32_t ah[4], al[4];
            ldsm4(ah, aX + ks * 32);
            ldsm4(al, aX + ks * 32 + dXlo);
            #pragma unroll
            for (int np = 0; np < 4; np++) {
                uint32_t ba = bW1 + (ks * 16 * W1S + np * 16) * 2;
                uint32_t bh[4], bl[4];
                ldsm4t(bh, ba);
                ldsm4t(bl, ba + dW1lo);
                mma_bf16(acc[2 * np],     ah, bh);
                mma_bf16(acc[2 * np],     ah, bl);
                mma_bf16(acc[2 * np],     al, bh);
                mma_bf16(acc[2 * np + 1], ah, bh + 2);
                mma_bf16(acc[2 * np + 1], ah, bl + 2);
                mma_bf16(acc[2 * np + 1], al, bh + 2);
            }
        }

        // ---- convert in registers: H = relu(acc + b1) -> A-fragments ----
        // A k-atom kp takes C n-atoms 2kp (-> a0,a1) and 2kp+1 (-> a2,a3)
        uint32_t ha[4][4], la[4][4];
        #pragma unroll
        for (int kp = 0; kp < 4; kp++) {
            #pragma unroll
            for (int j = 0; j < 2; j++) {
                int na = 2 * kp + j;
                const float* bp = &sb1a[c * 64 + 8 * na + bcol];
                float bb0 = bp[0], bb1 = bp[1];
                float f0 = fmaxf(acc[na][0] + bb0, 0.f);
                float f1 = fmaxf(acc[na][1] + bb1, 0.f);
                float f2 = fmaxf(acc[na][2] + bb0, 0.f);
                float f3 = fmaxf(acc[na][3] + bb1, 0.f);
                __nv_bfloat162 h01 = __floats2bfloat162_rn(f0, f1);
                float2 hf01 = __bfloat1622float2(h01);
                __nv_bfloat162 l01 = __floats2bfloat162_rn(f0 - hf01.x, f1 - hf01.y);
                __nv_bfloat162 h23 = __floats2bfloat162_rn(f2, f3);
                float2 hf23 = __bfloat1622float2(h23);
                __nv_bfloat162 l23 = __floats2bfloat162_rn(f2 - hf23.x, f3 - hf23.y);
                ha[kp][2 * j]     = *(uint32_t*)&h01;
                ha[kp][2 * j + 1] = *(uint32_t*)&h23;
                la[kp][2 * j]     = *(uint32_t*)&l01;
                la[kp][2 * j + 1] = *(uint32_t*)&l23;
            }
        }

        __syncthreads();     // all warps done reading W1 buffer
        if (c < NCK - 1) { ISSUE_W1(c + 1); CP_COMMIT(); }   // overlaps GEMM2
        CP_WAIT1();          // W2[c] done (this thread); W1[c+1] pending
        __syncthreads();     // W2[c] visible block-wide

        // ---- GEMM2: yacc += H(16x64) @ W2chunk(64x80), 3-term split ----
        #pragma unroll
        for (int kp = 0; kp < 4; kp++) {
            #pragma unroll
            for (int nb = 0; nb < 5; nb++) {
                uint32_t ba = bW2 + (kp * 16 * W2S + nb * 16) * 2;
                uint32_t bh[4], bl[4];
                ldsm4t(bh, ba);
                ldsm4t(bl, ba + dW2lo);
                mma_bf16(yacc[2 * nb],     ha[kp], bh);
                mma_bf16(yacc[2 * nb],     ha[kp], bl);
                mma_bf16(yacc[2 * nb],     la[kp], bh);
                mma_bf16(yacc[2 * nb + 1], ha[kp], bh + 2);
                mma_bf16(yacc[2 * nb + 1], ha[kp], bl + 2);
                mma_bf16(yacc[2 * nb + 1], la[kp], bh + 2);
            }
        }

        __syncthreads();     // all warps done reading W2 buffer
        if (c < NCK - 1) { ISSUE_W2(c + 1); CP_COMMIT(); }   // overlaps next GEMM1
    }

    // ---- write expert-output rows (y + b2) to slot buffer, non-atomic ----
    {
        int row0 = (wid << 4) + (lane >> 2);
        int row1 = row0 + 8;
        bool v0 = (start + row0 < n);
        bool v1 = (start + row1 < n);
        float* o0 = g_eo + (size_t)(pbase + start + row0) * D;
        float* o1 = g_eo + (size_t)(pbase + start + row1) * D;
        #pragma unroll
        for (int nb = 0; nb < 10; nb++) {
            int col = 8 * nb + bcol;
            float b20 = sb2[col], b21 = sb2[col + 1];
            if (v0) *(float2*)&o0[col] = make_float2(yacc[nb][0] + b20, yacc[nb][1] + b21);
            if (v1) *(float2*)&o1[col] = make_float2(yacc[nb][2] + b20, yacc[nb][3] + b21);
        }
    }
    #undef ISSUE_W1
    #undef ISSUE_W2
}

// ---------------------------------------------------------------------------
extern "C" void kernel_launch(void* const* d_in, const int* in_sizes, int n_in,
                              void* d_out, int out_size) {
    const float* x  = (const float*)d_in[0];
    const float* Wg = (const float*)d_in[1];
    const float* bg = (const float*)d_in[2];
    const float* W1 = (const float*)d_in[3];
    const float* b1 = (const float*)d_in[4];
    const float* W2 = (const float*)d_in[5];
    const float* b2 = (const float*)d_in[6];
    float* out = (float*)d_out;

    int T = in_sizes[0] / D;

    cudaFuncSetAttribute(ffn_kernel, cudaFuncAttributeMaxDynamicSharedMemorySize, SMEM_TOTAL);

    void *cntp, *bufAp;
    cudaGetSymbolAddress(&cntp,  g_cnt);
    cudaGetSymbolAddress(&bufAp, g_bufA);
    int*   cntb = (int*)cntp;
    float* bufA = (float*)bufAp;

    const int NPREP = E * D * HID + E * HID * D;   // 409600
    prep_kernel<<<(NPREP + 255) / 256, 256>>>(W1, W2);
    zero_kernel<<<1, 64>>>();

    int rb = (T + RTB - 1) / RTB;
    int GB = (2 * T) / TBK + E + 1;   // compact ffn grid upper bound

    for (int l = 0; l < NL; l++) {
        int mode = (l == 0) ? 2 : 3;
        router_kernel<<<rb, RTB>>>((l == 0) ? x : nullptr,
                                   cntb + (l - 1) * E,
                                   cntb + l * E,
                                   bufA,
                                   Wg + (size_t)l * D * E, bg + l * E,
                                   T, mode);
        ffn_kernel<<<GB, 256, SMEM_TOTAL>>>((l == 0) ? x : bufA,
                                            cntb + l * E, b1, b2);
    }
    // final combine-only pass -> d_out
    router_kernel<<<rb, RTB>>>(nullptr, cntb + (NL - 1) * E, cntb, out,
                               Wg, bg, T, 1);
}